// round 3
// baseline (speedup 1.0000x reference)
#include <cuda_runtime.h>
#include <math.h>

#define D 128
#define NMAX 20000
#define EMAX 640000
#define LN_EPS 1e-5f

// ---------------- device scratch (no allocs allowed) ----------------
__device__ float g_aggf[NMAX * D];     // segment-max result (0 for empty)
__device__ float g_h[NMAX * D];        // h after first LayerNorm
__device__ int   g_cnt[NMAX];          // per-node degree counters
__device__ int   g_off[NMAX + 1];      // CSR offsets
__device__ int   g_bsum[64];           // per-scan-block sums
__device__ int   g_pos[EMAX];          // per-edge slot within its dst bucket
__device__ int   g_src[EMAX];          // CSR-ordered source ids
__device__ float g_w[EMAX];            // CSR-ordered edge weights
__device__ int   g_i64;                // 1 if edge_index buffer is int64

__device__ __forceinline__ float gelu_exact(float v) { return v * normcdff(v); }

__device__ __forceinline__ void fma4(float4& acc, float a, const float4& w) {
    acc.x = fmaf(a, w.x, acc.x); acc.y = fmaf(a, w.y, acc.y);
    acc.z = fmaf(a, w.z, acc.z); acc.w = fmaf(a, w.w, acc.w);
}

// ---------------- K0: detect int64 + zero counters ----------------
__global__ void k_prep(const int* __restrict__ ei, int n) {
    int i = blockIdx.x * blockDim.x + threadIdx.x;
    if (i < n) g_cnt[i] = 0;
    if (blockIdx.x == 0) {
        __shared__ int bad;
        if (threadIdx.x == 0) bad = 0;
        __syncthreads();
        int any = 0;
        for (int j = threadIdx.x; j < 1024; j += blockDim.x)
            if (ei[2 * j + 1] != 0) any = 1;
        if (any) atomicOr(&bad, 1);
        __syncthreads();
        if (threadIdx.x == 0) g_i64 = (bad == 0) ? 1 : 0;
    }
}

__global__ void k_count(const int* __restrict__ ei, int e) {
    int i = blockIdx.x * blockDim.x + threadIdx.x;
    if (i >= e) return;
    int dst = g_i64 ? ei[2 * (e + i)] : ei[e + i];
    g_pos[i] = atomicAdd(&g_cnt[dst], 1);
}

// ---------------- parallel scan: pass 1 = per-block sums ----------------
__global__ void k_scan1(int n) {
    __shared__ int wsum[32];
    int i = blockIdx.x * 1024 + threadIdx.x;
    int lane = threadIdx.x & 31, wid = threadIdx.x >> 5;
    int v = (i < n) ? g_cnt[i] : 0;
    #pragma unroll
    for (int o = 16; o; o >>= 1) v += __shfl_xor_sync(0xffffffffu, v, o);
    if (lane == 0) wsum[wid] = v;
    __syncthreads();
    if (wid == 0) {
        int s = wsum[lane];
        #pragma unroll
        for (int o = 16; o; o >>= 1) s += __shfl_xor_sync(0xffffffffu, s, o);
        if (lane == 0) g_bsum[blockIdx.x] = s;
    }
}

// ---------------- pass 2: local exclusive scan + block prefix ----------------
__global__ void k_scan2(int n) {
    __shared__ int wsum[32];
    __shared__ int prefix_s;
    int tid = threadIdx.x, lane = tid & 31, wid = tid >> 5;
    int b = blockIdx.x;
    if (tid == 0) {
        int p = 0;
        for (int j = 0; j < b; j++) p += g_bsum[j];
        prefix_s = p;
    }
    int i = b * 1024 + tid;
    int v = (i < n) ? g_cnt[i] : 0;
    int s = v;
    #pragma unroll
    for (int o = 1; o < 32; o <<= 1) {
        int t = __shfl_up_sync(0xffffffffu, s, o);
        if (lane >= o) s += t;
    }
    if (lane == 31) wsum[wid] = s;
    __syncthreads();
    if (wid == 0) {
        int ws = wsum[lane];
        #pragma unroll
        for (int o = 1; o < 32; o <<= 1) {
            int t = __shfl_up_sync(0xffffffffu, ws, o);
            if (lane >= o) ws += t;
        }
        wsum[lane] = ws;
    }
    __syncthreads();
    int prefix = prefix_s;
    int excl = prefix + s - v + (wid > 0 ? wsum[wid - 1] : 0);
    if (i < n) g_off[i] = excl;
    if (b == gridDim.x - 1 && tid == 0) g_off[n] = prefix + wsum[31];
}

__global__ void k_place(const int* __restrict__ ei, const float* __restrict__ ew, int e) {
    int i = blockIdx.x * blockDim.x + threadIdx.x;
    if (i >= e) return;
    int src, dst;
    if (g_i64) { src = ei[2 * i]; dst = ei[2 * (e + i)]; }
    else       { src = ei[i];     dst = ei[e + i]; }
    int idx = g_off[dst] + g_pos[i];
    g_src[idx] = src;
    g_w[idx]   = ew[i];
}

// ---------------- per-node gather-max: one warp per node ----------------
__global__ void k_agg(const float* __restrict__ x, int n) {
    int wp = threadIdx.x >> 5, lane = threadIdx.x & 31;
    int node = blockIdx.x * 8 + wp;
    if (node >= n) return;
    int s0 = g_off[node], s1 = g_off[node + 1];
    const float4* x4 = (const float4*)x;
    float4 m = make_float4(-INFINITY, -INFINITY, -INFINITY, -INFINITY);
    int i = s0;
    for (; i + 3 < s1; i += 4) {
        int sa = g_src[i], sb = g_src[i + 1], sc = g_src[i + 2], sd = g_src[i + 3];
        float wa = g_w[i], wb = g_w[i + 1], wc = g_w[i + 2], wd = g_w[i + 3];
        float4 va = x4[sa * 32 + lane];
        float4 vb = x4[sb * 32 + lane];
        float4 vc = x4[sc * 32 + lane];
        float4 vd = x4[sd * 32 + lane];
        m.x = fmaxf(m.x, va.x * wa); m.y = fmaxf(m.y, va.y * wa);
        m.z = fmaxf(m.z, va.z * wa); m.w = fmaxf(m.w, va.w * wa);
        m.x = fmaxf(m.x, vb.x * wb); m.y = fmaxf(m.y, vb.y * wb);
        m.z = fmaxf(m.z, vb.z * wb); m.w = fmaxf(m.w, vb.w * wb);
        m.x = fmaxf(m.x, vc.x * wc); m.y = fmaxf(m.y, vc.y * wc);
        m.z = fmaxf(m.z, vc.z * wc); m.w = fmaxf(m.w, vc.w * wc);
        m.x = fmaxf(m.x, vd.x * wd); m.y = fmaxf(m.y, vd.y * wd);
        m.z = fmaxf(m.z, vd.z * wd); m.w = fmaxf(m.w, vd.w * wd);
    }
    for (; i < s1; i++) {
        int sa = g_src[i]; float wa = g_w[i];
        float4 va = x4[sa * 32 + lane];
        m.x = fmaxf(m.x, va.x * wa); m.y = fmaxf(m.y, va.y * wa);
        m.z = fmaxf(m.z, va.z * wa); m.w = fmaxf(m.w, va.w * wa);
    }
    if (s1 <= s0) m = make_float4(0.f, 0.f, 0.f, 0.f);
    ((float4*)g_aggf)[node * 32 + lane] = m;
}

// ---------------- K3: h = LN( gelu(agg@Wrel^T + b + x@Wroot^T) + x ) ----------------
// 256 threads = 16 rowT x 16 colT; thread tile 4 rows x 8 cols; chunk 64x128.
// K processed in two phases (agg, then x) reusing one A-buffer; x stays
// resident for the skip connection. Per-warp per-4k: 12 LDS.128 vs 128 FFMA.
__global__ void __launch_bounds__(256, 1)
k_gemm1(const float* __restrict__ x, const float* __restrict__ Wrel,
        const float* __restrict__ brel, const float* __restrict__ Wroot,
        const float* __restrict__ gamma, const float* __restrict__ beta, int n) {
    extern __shared__ float sm[];
    float* wtr = sm;                    // [128][132] Wrel^T
    float* wto = wtr + 128 * 132;       // [128][132] Wroot^T
    float* ab  = wto + 128 * 132;       // [64][132]  A buffer

    int tid = threadIdx.x;
    int colT = tid & 15, rowT = tid >> 4;
    int c0 = colT * 8, r0 = rowT * 4;

    for (int i = tid; i < 128 * 128; i += 256) {
        int c = i >> 7, k = i & 127;
        wtr[k * 132 + c] = Wrel[i];
        wto[k * 132 + c] = Wroot[i];
    }
    float4 bvA = *(const float4*)&brel[c0],  bvB = *(const float4*)&brel[c0 + 4];
    float4 gvA = *(const float4*)&gamma[c0], gvB = *(const float4*)&gamma[c0 + 4];
    float4 btA = *(const float4*)&beta[c0],  btB = *(const float4*)&beta[c0 + 4];
    __syncthreads();

    int nch = (n + 63) >> 6;
    for (int ch = blockIdx.x; ch < nch; ch += gridDim.x) {
        int row0 = ch << 6;
        float4 accA[4], accB[4];
        #pragma unroll
        for (int j = 0; j < 4; j++) {
            accA[j] = make_float4(0.f, 0.f, 0.f, 0.f);
            accB[j] = make_float4(0.f, 0.f, 0.f, 0.f);
        }

        // ---- phase 1: agg rows ----
        for (int i = tid; i < 64 * 32; i += 256) {
            int r = i >> 5, k4 = i & 31, gr = row0 + r;
            float4 v = (gr < n) ? ((const float4*)g_aggf)[gr * 32 + k4]
                                : make_float4(0.f, 0.f, 0.f, 0.f);
            *(float4*)&ab[r * 132 + k4 * 4] = v;
        }
        __syncthreads();
        #pragma unroll 2
        for (int k = 0; k < 128; k += 4) {
            float4 w0A = *(const float4*)&wtr[(k + 0) * 132 + c0];
            float4 w0B = *(const float4*)&wtr[(k + 0) * 132 + c0 + 4];
            float4 w1A = *(const float4*)&wtr[(k + 1) * 132 + c0];
            float4 w1B = *(const float4*)&wtr[(k + 1) * 132 + c0 + 4];
            float4 w2A = *(const float4*)&wtr[(k + 2) * 132 + c0];
            float4 w2B = *(const float4*)&wtr[(k + 2) * 132 + c0 + 4];
            float4 w3A = *(const float4*)&wtr[(k + 3) * 132 + c0];
            float4 w3B = *(const float4*)&wtr[(k + 3) * 132 + c0 + 4];
            #pragma unroll
            for (int j = 0; j < 4; j++) {
                float4 a = *(const float4*)&ab[(r0 + j) * 132 + k];
                fma4(accA[j], a.x, w0A); fma4(accB[j], a.x, w0B);
                fma4(accA[j], a.y, w1A); fma4(accB[j], a.y, w1B);
                fma4(accA[j], a.z, w2A); fma4(accB[j], a.z, w2B);
                fma4(accA[j], a.w, w3A); fma4(accB[j], a.w, w3B);
            }
        }
        __syncthreads();

        // ---- phase 2: x rows (stay resident for skip) ----
        for (int i = tid; i < 64 * 32; i += 256) {
            int r = i >> 5, k4 = i & 31, gr = row0 + r;
            float4 v = (gr < n) ? ((const float4*)x)[gr * 32 + k4]
                                : make_float4(0.f, 0.f, 0.f, 0.f);
            *(float4*)&ab[r * 132 + k4 * 4] = v;
        }
        __syncthreads();
        #pragma unroll 2
        for (int k = 0; k < 128; k += 4) {
            float4 w0A = *(const float4*)&wto[(k + 0) * 132 + c0];
            float4 w0B = *(const float4*)&wto[(k + 0) * 132 + c0 + 4];
            float4 w1A = *(const float4*)&wto[(k + 1) * 132 + c0];
            float4 w1B = *(const float4*)&wto[(k + 1) * 132 + c0 + 4];
            float4 w2A = *(const float4*)&wto[(k + 2) * 132 + c0];
            float4 w2B = *(const float4*)&wto[(k + 2) * 132 + c0 + 4];
            float4 w3A = *(const float4*)&wto[(k + 3) * 132 + c0];
            float4 w3B = *(const float4*)&wto[(k + 3) * 132 + c0 + 4];
            #pragma unroll
            for (int j = 0; j < 4; j++) {
                float4 a = *(const float4*)&ab[(r0 + j) * 132 + k];
                fma4(accA[j], a.x, w0A); fma4(accB[j], a.x, w0B);
                fma4(accA[j], a.y, w1A); fma4(accB[j], a.y, w1B);
                fma4(accA[j], a.z, w2A); fma4(accB[j], a.z, w2B);
                fma4(accA[j], a.w, w3A); fma4(accB[j], a.w, w3B);
            }
        }

        // ---- epilogue: gelu + skip + LN ----
        #pragma unroll
        for (int j = 0; j < 4; j++) {
            int r = row0 + r0 + j;
            float4 skA = *(const float4*)&ab[(r0 + j) * 132 + c0];
            float4 skB = *(const float4*)&ab[(r0 + j) * 132 + c0 + 4];
            float4 hA, hB;
            hA.x = gelu_exact(accA[j].x + bvA.x) + skA.x;
            hA.y = gelu_exact(accA[j].y + bvA.y) + skA.y;
            hA.z = gelu_exact(accA[j].z + bvA.z) + skA.z;
            hA.w = gelu_exact(accA[j].w + bvA.w) + skA.w;
            hB.x = gelu_exact(accB[j].x + bvB.x) + skB.x;
            hB.y = gelu_exact(accB[j].y + bvB.y) + skB.y;
            hB.z = gelu_exact(accB[j].z + bvB.z) + skB.z;
            hB.w = gelu_exact(accB[j].w + bvB.w) + skB.w;
            float s = hA.x + hA.y + hA.z + hA.w + hB.x + hB.y + hB.z + hB.w;
            float q = hA.x * hA.x + hA.y * hA.y + hA.z * hA.z + hA.w * hA.w
                    + hB.x * hB.x + hB.y * hB.y + hB.z * hB.z + hB.w * hB.w;
            #pragma unroll
            for (int o = 8; o; o >>= 1) {
                s += __shfl_xor_sync(0xffffffffu, s, o);
                q += __shfl_xor_sync(0xffffffffu, q, o);
            }
            float mu = s * (1.f / D);
            float var = fmaxf(q * (1.f / D) - mu * mu, 0.f);
            float rs = rsqrtf(var + LN_EPS);
            float4 yA, yB;
            yA.x = (hA.x - mu) * rs * gvA.x + btA.x;
            yA.y = (hA.y - mu) * rs * gvA.y + btA.y;
            yA.z = (hA.z - mu) * rs * gvA.z + btA.z;
            yA.w = (hA.w - mu) * rs * gvA.w + btA.w;
            yB.x = (hB.x - mu) * rs * gvB.x + btB.x;
            yB.y = (hB.y - mu) * rs * gvB.y + btB.y;
            yB.z = (hB.z - mu) * rs * gvB.z + btB.z;
            yB.w = (hB.w - mu) * rs * gvB.w + btB.w;
            if (r < n) {
                *(float4*)&g_h[r * 128 + c0]     = yA;
                *(float4*)&g_h[r * 128 + c0 + 4] = yB;
            }
        }
        __syncthreads();
    }
}

// ---------------- K4: out = LN( gelu(h@linW^T + lb) + h ) ----------------
__global__ void __launch_bounds__(256, 2)
k_gemm2(const float* __restrict__ lw, const float* __restrict__ lb,
        const float* __restrict__ gamma, const float* __restrict__ beta,
        float* __restrict__ out, int n) {
    extern __shared__ float sm[];
    float* wt = sm;                 // [128][132]
    float* ab = wt + 128 * 132;     // [64][132]

    int tid = threadIdx.x;
    int colT = tid & 15, rowT = tid >> 4;
    int c0 = colT * 8, r0 = rowT * 4;

    for (int i = tid; i < 128 * 128; i += 256) {
        int c = i >> 7, k = i & 127;
        wt[k * 132 + c] = lw[i];
    }
    float4 bvA = *(const float4*)&lb[c0],    bvB = *(const float4*)&lb[c0 + 4];
    float4 gvA = *(const float4*)&gamma[c0], gvB = *(const float4*)&gamma[c0 + 4];
    float4 btA = *(const float4*)&beta[c0],  btB = *(const float4*)&beta[c0 + 4];
    __syncthreads();

    int nch = (n + 63) >> 6;
    for (int ch = blockIdx.x; ch < nch; ch += gridDim.x) {
        int row0 = ch << 6;
        for (int i = tid; i < 64 * 32; i += 256) {
            int r = i >> 5, k4 = i & 31, gr = row0 + r;
            float4 v = (gr < n) ? ((const float4*)g_h)[gr * 32 + k4]
                                : make_float4(0.f, 0.f, 0.f, 0.f);
            *(float4*)&ab[r * 132 + k4 * 4] = v;
        }
        __syncthreads();

        float4 accA[4], accB[4];
        #pragma unroll
        for (int j = 0; j < 4; j++) {
            accA[j] = make_float4(0.f, 0.f, 0.f, 0.f);
            accB[j] = make_float4(0.f, 0.f, 0.f, 0.f);
        }
        #pragma unroll 2
        for (int k = 0; k < 128; k += 4) {
            float4 w0A = *(const float4*)&wt[(k + 0) * 132 + c0];
            float4 w0B = *(const float4*)&wt[(k + 0) * 132 + c0 + 4];
            float4 w1A = *(const float4*)&wt[(k + 1) * 132 + c0];
            float4 w1B = *(const float4*)&wt[(k + 1) * 132 + c0 + 4];
            float4 w2A = *(const float4*)&wt[(k + 2) * 132 + c0];
            float4 w2B = *(const float4*)&wt[(k + 2) * 132 + c0 + 4];
            float4 w3A = *(const float4*)&wt[(k + 3) * 132 + c0];
            float4 w3B = *(const float4*)&wt[(k + 3) * 132 + c0 + 4];
            #pragma unroll
            for (int j = 0; j < 4; j++) {
                float4 a = *(const float4*)&ab[(r0 + j) * 132 + k];
                fma4(accA[j], a.x, w0A); fma4(accB[j], a.x, w0B);
                fma4(accA[j], a.y, w1A); fma4(accB[j], a.y, w1B);
                fma4(accA[j], a.z, w2A); fma4(accB[j], a.z, w2B);
                fma4(accA[j], a.w, w3A); fma4(accB[j], a.w, w3B);
            }
        }

        #pragma unroll
        for (int j = 0; j < 4; j++) {
            int r = row0 + r0 + j;
            float4 skA = *(const float4*)&ab[(r0 + j) * 132 + c0];
            float4 skB = *(const float4*)&ab[(r0 + j) * 132 + c0 + 4];
            float4 hA, hB;
            hA.x = gelu_exact(accA[j].x + bvA.x) + skA.x;
            hA.y = gelu_exact(accA[j].y + bvA.y) + skA.y;
            hA.z = gelu_exact(accA[j].z + bvA.z) + skA.z;
            hA.w = gelu_exact(accA[j].w + bvA.w) + skA.w;
            hB.x = gelu_exact(accB[j].x + bvB.x) + skB.x;
            hB.y = gelu_exact(accB[j].y + bvB.y) + skB.y;
            hB.z = gelu_exact(accB[j].z + bvB.z) + skB.z;
            hB.w = gelu_exact(accB[j].w + bvB.w) + skB.w;
            float s = hA.x + hA.y + hA.z + hA.w + hB.x + hB.y + hB.z + hB.w;
            float q = hA.x * hA.x + hA.y * hA.y + hA.z * hA.z + hA.w * hA.w
                    + hB.x * hB.x + hB.y * hB.y + hB.z * hB.z + hB.w * hB.w;
            #pragma unroll
            for (int o = 8; o; o >>= 1) {
                s += __shfl_xor_sync(0xffffffffu, s, o);
                q += __shfl_xor_sync(0xffffffffu, q, o);
            }
            float mu = s * (1.f / D);
            float var = fmaxf(q * (1.f / D) - mu * mu, 0.f);
            float rs = rsqrtf(var + LN_EPS);
            float4 yA, yB;
            yA.x = (hA.x - mu) * rs * gvA.x + btA.x;
            yA.y = (hA.y - mu) * rs * gvA.y + btA.y;
            yA.z = (hA.z - mu) * rs * gvA.z + btA.z;
            yA.w = (hA.w - mu) * rs * gvA.w + btA.w;
            yB.x = (hB.x - mu) * rs * gvB.x + btB.x;
            yB.y = (hB.y - mu) * rs * gvB.y + btB.y;
            yB.z = (hB.z - mu) * rs * gvB.z + btB.z;
            yB.w = (hB.w - mu) * rs * gvB.w + btB.w;
            if (r < n) {
                *(float4*)&out[r * 128 + c0]     = yA;
                *(float4*)&out[r * 128 + c0 + 4] = yB;
            }
        }
        __syncthreads();
    }
}

// ---------------- launch ----------------
extern "C" void kernel_launch(void* const* d_in, const int* in_sizes, int n_in,
                              void* d_out, int out_size) {
    const float* x     = (const float*)d_in[0];
    const int*   ei    = (const int*)d_in[1];
    const float* ew    = (const float*)d_in[2];
    const float* Wrel  = (const float*)d_in[3];
    const float* brel  = (const float*)d_in[4];
    const float* Wroot = (const float*)d_in[5];
    const float* linW  = (const float*)d_in[6];
    const float* linb  = (const float*)d_in[7];
    const float* gamma = (const float*)d_in[8];
    const float* beta  = (const float*)d_in[9];
    float* out = (float*)d_out;

    int n = in_sizes[0] / D;
    int e = in_sizes[2];
    int nsb = (n + 1023) / 1024;

    size_t smem1 = (size_t)(2 * 128 * 132 + 64 * 132) * 4;  // 168,960 B
    size_t smem2 = (size_t)(128 * 132 + 64 * 132) * 4;      // 101,376 B
    cudaFuncSetAttribute(k_gemm1, cudaFuncAttributeMaxDynamicSharedMemorySize, (int)smem1);
    cudaFuncSetAttribute(k_gemm2, cudaFuncAttributeMaxDynamicSharedMemorySize, (int)smem2);

    k_prep<<<(n + 255) / 256, 256>>>(ei, n);
    k_count<<<(e + 255) / 256, 256>>>(ei, e);
    k_scan1<<<nsb, 1024>>>(n);
    k_scan2<<<nsb, 1024>>>(n);
    k_place<<<(e + 255) / 256, 256>>>(ei, ew, e);
    k_agg<<<(n + 7) / 8, 256>>>(x, n);
    k_gemm1<<<148, 256, smem1>>>(x, Wrel, brel, Wroot, gamma, beta, n);
    k_gemm2<<<296, 256, smem2>>>(linW, linb, gamma, beta, out, n);
    if (out_size >= n * D + e)
        cudaMemcpyAsync(out + (size_t)n * D, ew, (size_t)e * sizeof(float),
                        cudaMemcpyDeviceToDevice);
}

// round 8
// speedup vs baseline: 1.2194x; 1.2194x over previous
#include <cuda_runtime.h>
#include <math.h>

#define D 128
#define NMAX 20000
#define EMAX 640000
#define LN_EPS 1e-5f

// ---------------- device scratch (no allocs allowed) ----------------
__device__ float g_aggf[NMAX * D];     // segment-max result (0 for empty)
__device__ float g_h[NMAX * D];        // h after first LayerNorm
__device__ int   g_cnt[NMAX];          // per-node degree counters
__device__ int   g_off[NMAX + 1];      // CSR offsets
__device__ int   g_bsum[64];           // per-scan-block sums
__device__ int   g_pos[EMAX];          // per-edge slot within its dst bucket
__device__ int   g_src[EMAX];          // CSR-ordered source ids
__device__ float g_w[EMAX];            // CSR-ordered edge weights
__device__ int   g_i64;                // 1 if edge_index buffer is int64

__device__ __forceinline__ float gelu_exact(float v) { return v * normcdff(v); }

__device__ __forceinline__ void fma4(float4& acc, float a, const float4& w) {
    acc.x = fmaf(a, w.x, acc.x); acc.y = fmaf(a, w.y, acc.y);
    acc.z = fmaf(a, w.z, acc.z); acc.w = fmaf(a, w.w, acc.w);
}

// ---------------- K0: detect int64 + zero counters ----------------
__global__ void k_prep(const int* __restrict__ ei, int n) {
    int i = blockIdx.x * blockDim.x + threadIdx.x;
    if (i < n) g_cnt[i] = 0;
    if (blockIdx.x == 0) {
        __shared__ int bad;
        if (threadIdx.x == 0) bad = 0;
        __syncthreads();
        int any = 0;
        for (int j = threadIdx.x; j < 1024; j += blockDim.x)
            if (ei[2 * j + 1] != 0) any = 1;
        if (any) atomicOr(&bad, 1);
        __syncthreads();
        if (threadIdx.x == 0) g_i64 = (bad == 0) ? 1 : 0;
    }
}

__global__ void k_count(const int* __restrict__ ei, int e) {
    int i = blockIdx.x * blockDim.x + threadIdx.x;
    if (i >= e) return;
    int dst = g_i64 ? ei[2 * (e + i)] : ei[e + i];
    g_pos[i] = atomicAdd(&g_cnt[dst], 1);
}

// ---------------- parallel scan: pass 1 = per-block sums ----------------
__global__ void k_scan1(int n) {
    __shared__ int wsum[32];
    int i = blockIdx.x * 1024 + threadIdx.x;
    int lane = threadIdx.x & 31, wid = threadIdx.x >> 5;
    int v = (i < n) ? g_cnt[i] : 0;
    #pragma unroll
    for (int o = 16; o; o >>= 1) v += __shfl_xor_sync(0xffffffffu, v, o);
    if (lane == 0) wsum[wid] = v;
    __syncthreads();
    if (wid == 0) {
        int s = wsum[lane];
        #pragma unroll
        for (int o = 16; o; o >>= 1) s += __shfl_xor_sync(0xffffffffu, s, o);
        if (lane == 0) g_bsum[blockIdx.x] = s;
    }
}

// ---------------- pass 2: local exclusive scan + block prefix ----------------
__global__ void k_scan2(int n) {
    __shared__ int wsum[32];
    __shared__ int prefix_s;
    int tid = threadIdx.x, lane = tid & 31, wid = tid >> 5;
    int b = blockIdx.x;
    if (tid == 0) {
        int p = 0;
        for (int j = 0; j < b; j++) p += g_bsum[j];
        prefix_s = p;
    }
    int i = b * 1024 + tid;
    int v = (i < n) ? g_cnt[i] : 0;
    int s = v;
    #pragma unroll
    for (int o = 1; o < 32; o <<= 1) {
        int t = __shfl_up_sync(0xffffffffu, s, o);
        if (lane >= o) s += t;
    }
    if (lane == 31) wsum[wid] = s;
    __syncthreads();
    if (wid == 0) {
        int ws = wsum[lane];
        #pragma unroll
        for (int o = 1; o < 32; o <<= 1) {
            int t = __shfl_up_sync(0xffffffffu, ws, o);
            if (lane >= o) ws += t;
        }
        wsum[lane] = ws;
    }
    __syncthreads();
    int prefix = prefix_s;
    int excl = prefix + s - v + (wid > 0 ? wsum[wid - 1] : 0);
    if (i < n) g_off[i] = excl;
    if (b == gridDim.x - 1 && tid == 0) g_off[n] = prefix + wsum[31];
}

__global__ void k_place(const int* __restrict__ ei, const float* __restrict__ ew, int e) {
    int i = blockIdx.x * blockDim.x + threadIdx.x;
    if (i >= e) return;
    int src, dst;
    if (g_i64) { src = ei[2 * i]; dst = ei[2 * (e + i)]; }
    else       { src = ei[i];     dst = ei[e + i]; }
    int idx = g_off[dst] + g_pos[i];
    g_src[idx] = src;
    g_w[idx]   = ew[i];
}

// ---------------- per-node gather-max: one warp per node ----------------
__global__ void k_agg(const float* __restrict__ x, int n) {
    int wp = threadIdx.x >> 5, lane = threadIdx.x & 31;
    int node = blockIdx.x * 8 + wp;
    if (node >= n) return;
    int s0 = g_off[node], s1 = g_off[node + 1];
    const float4* x4 = (const float4*)x;
    float4 m = make_float4(-INFINITY, -INFINITY, -INFINITY, -INFINITY);
    int i = s0;
    for (; i + 3 < s1; i += 4) {
        int sa = g_src[i], sb = g_src[i + 1], sc = g_src[i + 2], sd = g_src[i + 3];
        float wa = g_w[i], wb = g_w[i + 1], wc = g_w[i + 2], wd = g_w[i + 3];
        float4 va = x4[sa * 32 + lane];
        float4 vb = x4[sb * 32 + lane];
        float4 vc = x4[sc * 32 + lane];
        float4 vd = x4[sd * 32 + lane];
        m.x = fmaxf(m.x, va.x * wa); m.y = fmaxf(m.y, va.y * wa);
        m.z = fmaxf(m.z, va.z * wa); m.w = fmaxf(m.w, va.w * wa);
        m.x = fmaxf(m.x, vb.x * wb); m.y = fmaxf(m.y, vb.y * wb);
        m.z = fmaxf(m.z, vb.z * wb); m.w = fmaxf(m.w, vb.w * wb);
        m.x = fmaxf(m.x, vc.x * wc); m.y = fmaxf(m.y, vc.y * wc);
        m.z = fmaxf(m.z, vc.z * wc); m.w = fmaxf(m.w, vc.w * wc);
        m.x = fmaxf(m.x, vd.x * wd); m.y = fmaxf(m.y, vd.y * wd);
        m.z = fmaxf(m.z, vd.z * wd); m.w = fmaxf(m.w, vd.w * wd);
    }
    for (; i < s1; i++) {
        int sa = g_src[i]; float wa = g_w[i];
        float4 va = x4[sa * 32 + lane];
        m.x = fmaxf(m.x, va.x * wa); m.y = fmaxf(m.y, va.y * wa);
        m.z = fmaxf(m.z, va.z * wa); m.w = fmaxf(m.w, va.w * wa);
    }
    if (s1 <= s0) m = make_float4(0.f, 0.f, 0.f, 0.f);
    ((float4*)g_aggf)[node * 32 + lane] = m;
}

// ---------------- K3: h = LN( gelu(agg@Wrel^T + b + x@Wroot^T) + x ) ----------------
// 256 threads; chunk = 32 rows x 128 cols; thread tile 4 rows x 4 cols.
// (round-2 proven design: 625 chunks -> good balance, single-phase K)
__global__ void __launch_bounds__(256, 1)
k_gemm1(const float* __restrict__ x, const float* __restrict__ Wrel,
        const float* __restrict__ brel, const float* __restrict__ Wroot,
        const float* __restrict__ gamma, const float* __restrict__ beta, int n) {
    extern __shared__ float sm[];
    float* wtr = sm;                    // [128][132] transposed W_rel
    float* wto = wtr + 128 * 132;       // [128][132] transposed W_root
    float* asr = wto + 128 * 132;       // [32][132]  agg rows
    float* aso = asr + 32 * 132;        // [32][132]  x rows (skip source)

    int tid = threadIdx.x, lane = tid & 31, wp = tid >> 5;
    int c0 = lane * 4, r0 = wp * 4;

    for (int i = tid; i < 128 * 128; i += 256) {
        int c = i >> 7, k = i & 127;
        wtr[k * 132 + c] = Wrel[i];
        wto[k * 132 + c] = Wroot[i];
    }
    float4 bv = *(const float4*)&brel[c0];
    float4 gv = *(const float4*)&gamma[c0];
    float4 bt = *(const float4*)&beta[c0];
    __syncthreads();

    int nch = (n + 31) >> 5;
    for (int ch = blockIdx.x; ch < nch; ch += gridDim.x) {
        int row0 = ch << 5;
        for (int i = tid; i < 32 * 128; i += 256) {
            int r = i >> 7, k = i & 127, gr = row0 + r;
            float av = 0.f, xv = 0.f;
            if (gr < n) { av = g_aggf[gr * 128 + k]; xv = x[gr * 128 + k]; }
            asr[r * 132 + k] = av;
            aso[r * 132 + k] = xv;
        }
        __syncthreads();

        float4 acc[4];
        #pragma unroll
        for (int j = 0; j < 4; j++) acc[j] = make_float4(0.f, 0.f, 0.f, 0.f);

        #pragma unroll 2
        for (int k = 0; k < 128; k += 4) {
            float4 wr0 = *(const float4*)&wtr[(k + 0) * 132 + c0];
            float4 wr1 = *(const float4*)&wtr[(k + 1) * 132 + c0];
            float4 wr2 = *(const float4*)&wtr[(k + 2) * 132 + c0];
            float4 wr3 = *(const float4*)&wtr[(k + 3) * 132 + c0];
            float4 wo0 = *(const float4*)&wto[(k + 0) * 132 + c0];
            float4 wo1 = *(const float4*)&wto[(k + 1) * 132 + c0];
            float4 wo2 = *(const float4*)&wto[(k + 2) * 132 + c0];
            float4 wo3 = *(const float4*)&wto[(k + 3) * 132 + c0];
            #pragma unroll
            for (int j = 0; j < 4; j++) {
                float4 a1 = *(const float4*)&asr[(r0 + j) * 132 + k];
                float4 a2 = *(const float4*)&aso[(r0 + j) * 132 + k];
                fma4(acc[j], a1.x, wr0); fma4(acc[j], a2.x, wo0);
                fma4(acc[j], a1.y, wr1); fma4(acc[j], a2.y, wo1);
                fma4(acc[j], a1.z, wr2); fma4(acc[j], a2.z, wo2);
                fma4(acc[j], a1.w, wr3); fma4(acc[j], a2.w, wo3);
            }
        }

        #pragma unroll
        for (int j = 0; j < 4; j++) {
            int r = row0 + r0 + j;
            float4 sk = *(const float4*)&aso[(r0 + j) * 132 + c0];
            float4 h;
            h.x = gelu_exact(acc[j].x + bv.x) + sk.x;
            h.y = gelu_exact(acc[j].y + bv.y) + sk.y;
            h.z = gelu_exact(acc[j].z + bv.z) + sk.z;
            h.w = gelu_exact(acc[j].w + bv.w) + sk.w;
            float s = h.x + h.y + h.z + h.w;
            float q = h.x * h.x + h.y * h.y + h.z * h.z + h.w * h.w;
            #pragma unroll
            for (int o = 16; o; o >>= 1) {
                s += __shfl_xor_sync(0xffffffffu, s, o);
                q += __shfl_xor_sync(0xffffffffu, q, o);
            }
            float mu = s * (1.f / D);
            float var = fmaxf(q * (1.f / D) - mu * mu, 0.f);
            float rs = rsqrtf(var + LN_EPS);
            float4 y;
            y.x = (h.x - mu) * rs * gv.x + bt.x;
            y.y = (h.y - mu) * rs * gv.y + bt.y;
            y.z = (h.z - mu) * rs * gv.z + bt.z;
            y.w = (h.w - mu) * rs * gv.w + bt.w;
            if (r < n) *(float4*)&g_h[r * 128 + c0] = y;
        }
        __syncthreads();
    }
}

// ---------------- K4: out = LN( gelu(h@linW^T + lb) + h ) ----------------
__global__ void __launch_bounds__(256, 2)
k_gemm2(const float* __restrict__ lw, const float* __restrict__ lb,
        const float* __restrict__ gamma, const float* __restrict__ beta,
        float* __restrict__ out, int n) {
    extern __shared__ float sm[];
    float* wt = sm;                 // [128][132]
    float* as = wt + 128 * 132;     // [32][132] h rows (also skip source)

    int tid = threadIdx.x, lane = tid & 31, wp = tid >> 5;
    int c0 = lane * 4, r0 = wp * 4;

    for (int i = tid; i < 128 * 128; i += 256) {
        int c = i >> 7, k = i & 127;
        wt[k * 132 + c] = lw[i];
    }
    float4 bv = *(const float4*)&lb[c0];
    float4 gv = *(const float4*)&gamma[c0];
    float4 bt = *(const float4*)&beta[c0];
    __syncthreads();

    int nch = (n + 31) >> 5;
    for (int ch = blockIdx.x; ch < nch; ch += gridDim.x) {
        int row0 = ch << 5;
        for (int i = tid; i < 32 * 128; i += 256) {
            int r = i >> 7, k = i & 127, gr = row0 + r;
            as[r * 132 + k] = (gr < n) ? g_h[gr * 128 + k] : 0.f;
        }
        __syncthreads();

        float4 acc[4];
        #pragma unroll
        for (int j = 0; j < 4; j++) acc[j] = make_float4(0.f, 0.f, 0.f, 0.f);

        #pragma unroll 2
        for (int k = 0; k < 128; k += 4) {
            float4 w0 = *(const float4*)&wt[(k + 0) * 132 + c0];
            float4 w1 = *(const float4*)&wt[(k + 1) * 132 + c0];
            float4 w2 = *(const float4*)&wt[(k + 2) * 132 + c0];
            float4 w3 = *(const float4*)&wt[(k + 3) * 132 + c0];
            #pragma unroll
            for (int j = 0; j < 4; j++) {
                float4 a1 = *(const float4*)&as[(r0 + j) * 132 + k];
                fma4(acc[j], a1.x, w0);
                fma4(acc[j], a1.y, w1);
                fma4(acc[j], a1.z, w2);
                fma4(acc[j], a1.w, w3);
            }
        }

        #pragma unroll
        for (int j = 0; j < 4; j++) {
            int r = row0 + r0 + j;
            float4 sk = *(const float4*)&as[(r0 + j) * 132 + c0];
            float4 h;
            h.x = gelu_exact(acc[j].x + bv.x) + sk.x;
            h.y = gelu_exact(acc[j].y + bv.y) + sk.y;
            h.z = gelu_exact(acc[j].z + bv.z) + sk.z;
            h.w = gelu_exact(acc[j].w + bv.w) + sk.w;
            float s = h.x + h.y + h.z + h.w;
            float q = h.x * h.x + h.y * h.y + h.z * h.z + h.w * h.w;
            #pragma unroll
            for (int o = 16; o; o >>= 1) {
                s += __shfl_xor_sync(0xffffffffu, s, o);
                q += __shfl_xor_sync(0xffffffffu, q, o);
            }
            float mu = s * (1.f / D);
            float var = fmaxf(q * (1.f / D) - mu * mu, 0.f);
            float rs = rsqrtf(var + LN_EPS);
            float4 y;
            y.x = (h.x - mu) * rs * gv.x + bt.x;
            y.y = (h.y - mu) * rs * gv.y + bt.y;
            y.z = (h.z - mu) * rs * gv.z + bt.z;
            y.w = (h.w - mu) * rs * gv.w + bt.w;
            if (r < n) *(float4*)&out[r * 128 + c0] = y;
        }
        __syncthreads();
    }
}

// ---------------- launch ----------------
extern "C" void kernel_launch(void* const* d_in, const int* in_sizes, int n_in,
                              void* d_out, int out_size) {
    const float* x     = (const float*)d_in[0];
    const int*   ei    = (const int*)d_in[1];
    const float* ew    = (const float*)d_in[2];
    const float* Wrel  = (const float*)d_in[3];
    const float* brel  = (const float*)d_in[4];
    const float* Wroot = (const float*)d_in[5];
    const float* linW  = (const float*)d_in[6];
    const float* linb  = (const float*)d_in[7];
    const float* gamma = (const float*)d_in[8];
    const float* beta  = (const float*)d_in[9];
    float* out = (float*)d_out;

    int n = in_sizes[0] / D;
    int e = in_sizes[2];
    int nsb = (n + 1023) / 1024;

    size_t smem1 = (size_t)(2 * 128 * 132 + 2 * 32 * 132) * 4;  // 168,960 B
    size_t smem2 = (size_t)(128 * 132 + 32 * 132) * 4;          //  84,480 B
    cudaFuncSetAttribute(k_gemm1, cudaFuncAttributeMaxDynamicSharedMemorySize, (int)smem1);
    cudaFuncSetAttribute(k_gemm2, cudaFuncAttributeMaxDynamicSharedMemorySize, (int)smem2);

    k_prep<<<(n + 255) / 256, 256>>>(ei, n);
    k_count<<<(e + 255) / 256, 256>>>(ei, e);
    k_scan1<<<nsb, 1024>>>(n);
    k_scan2<<<nsb, 1024>>>(n);
    k_place<<<(e + 255) / 256, 256>>>(ei, ew, e);
    k_agg<<<(n + 7) / 8, 256>>>(x, n);
    k_gemm1<<<148, 256, smem1>>>(x, Wrel, brel, Wroot, gamma, beta, n);
    k_gemm2<<<296, 256, smem2>>>(linW, linb, gamma, beta, out, n);
    if (out_size >= n * D + e)
        cudaMemcpyAsync(out + (size_t)n * D, ew, (size_t)e * sizeof(float),
                        cudaMemcpyDeviceToDevice);
}

// round 13
// speedup vs baseline: 1.3402x; 1.0991x over previous
#include <cuda_runtime.h>
#include <cuda_bf16.h>
#include <math.h>
#include <stdint.h>

#define D 128
#define NMAX 20000
#define EMAX 640000
#define LN_EPS 1e-5f

// ---------------- device scratch (no allocs allowed) ----------------
__device__ float g_aggf[NMAX * D];     // segment-max result (0 for empty)
__device__ float g_h[NMAX * D];        // h after first LayerNorm
__device__ int   g_cnt[NMAX];          // per-node degree counters
__device__ int   g_off[NMAX + 1];      // CSR offsets
__device__ int   g_bsum[64];           // per-scan-block sums
__device__ int   g_pos[EMAX];          // per-edge slot within its dst bucket
__device__ int   g_src[EMAX];          // CSR-ordered source ids
__device__ float g_w[EMAX];            // CSR-ordered edge weights
__device__ int   g_i64;                // 1 if edge_index buffer is int64

__device__ __forceinline__ float gelu_exact(float v) { return v * normcdff(v); }

// ---------------- K0: detect int64 + zero counters ----------------
__global__ void k_prep(const int* __restrict__ ei, int n) {
    int i = blockIdx.x * blockDim.x + threadIdx.x;
    if (i < n) g_cnt[i] = 0;
    if (blockIdx.x == 0) {
        __shared__ int bad;
        if (threadIdx.x == 0) bad = 0;
        __syncthreads();
        int any = 0;
        for (int j = threadIdx.x; j < 1024; j += blockDim.x)
            if (ei[2 * j + 1] != 0) any = 1;
        if (any) atomicOr(&bad, 1);
        __syncthreads();
        if (threadIdx.x == 0) g_i64 = (bad == 0) ? 1 : 0;
    }
}

__global__ void k_count(const int* __restrict__ ei, int e) {
    int i = blockIdx.x * blockDim.x + threadIdx.x;
    if (i >= e) return;
    int dst = g_i64 ? ei[2 * (e + i)] : ei[e + i];
    g_pos[i] = atomicAdd(&g_cnt[dst], 1);
}

// ---------------- parallel scan ----------------
__global__ void k_scan1(int n) {
    __shared__ int wsum[32];
    int i = blockIdx.x * 1024 + threadIdx.x;
    int lane = threadIdx.x & 31, wid = threadIdx.x >> 5;
    int v = (i < n) ? g_cnt[i] : 0;
    #pragma unroll
    for (int o = 16; o; o >>= 1) v += __shfl_xor_sync(0xffffffffu, v, o);
    if (lane == 0) wsum[wid] = v;
    __syncthreads();
    if (wid == 0) {
        int s = wsum[lane];
        #pragma unroll
        for (int o = 16; o; o >>= 1) s += __shfl_xor_sync(0xffffffffu, s, o);
        if (lane == 0) g_bsum[blockIdx.x] = s;
    }
}

__global__ void k_scan2(int n) {
    __shared__ int wsum[32];
    __shared__ int prefix_s;
    int tid = threadIdx.x, lane = tid & 31, wid = tid >> 5;
    int b = blockIdx.x;
    if (tid == 0) {
        int p = 0;
        for (int j = 0; j < b; j++) p += g_bsum[j];
        prefix_s = p;
    }
    int i = b * 1024 + tid;
    int v = (i < n) ? g_cnt[i] : 0;
    int s = v;
    #pragma unroll
    for (int o = 1; o < 32; o <<= 1) {
        int t = __shfl_up_sync(0xffffffffu, s, o);
        if (lane >= o) s += t;
    }
    if (lane == 31) wsum[wid] = s;
    __syncthreads();
    if (wid == 0) {
        int ws = wsum[lane];
        #pragma unroll
        for (int o = 1; o < 32; o <<= 1) {
            int t = __shfl_up_sync(0xffffffffu, ws, o);
            if (lane >= o) ws += t;
        }
        wsum[lane] = ws;
    }
    __syncthreads();
    int prefix = prefix_s;
    int excl = prefix + s - v + (wid > 0 ? wsum[wid - 1] : 0);
    if (i < n) g_off[i] = excl;
    if (b == gridDim.x - 1 && tid == 0) g_off[n] = prefix + wsum[31];
}

__global__ void k_place(const int* __restrict__ ei, const float* __restrict__ ew, int e) {
    int i = blockIdx.x * blockDim.x + threadIdx.x;
    if (i >= e) return;
    int src, dst;
    if (g_i64) { src = ei[2 * i]; dst = ei[2 * (e + i)]; }
    else       { src = ei[i];     dst = ei[e + i]; }
    int idx = g_off[dst] + g_pos[i];
    g_src[idx] = src;
    g_w[idx]   = ew[i];
}

// ---------------- per-node gather-max: one warp per node ----------------
__global__ void k_agg(const float* __restrict__ x, int n) {
    int wp = threadIdx.x >> 5, lane = threadIdx.x & 31;
    int node = blockIdx.x * 8 + wp;
    if (node >= n) return;
    int s0 = g_off[node], s1 = g_off[node + 1];
    const float4* x4 = (const float4*)x;
    float4 m = make_float4(-INFINITY, -INFINITY, -INFINITY, -INFINITY);
    int i = s0;
    for (; i + 3 < s1; i += 4) {
        int sa = g_src[i], sb = g_src[i + 1], sc = g_src[i + 2], sd = g_src[i + 3];
        float wa = g_w[i], wb = g_w[i + 1], wc = g_w[i + 2], wd = g_w[i + 3];
        float4 va = x4[sa * 32 + lane];
        float4 vb = x4[sb * 32 + lane];
        float4 vc = x4[sc * 32 + lane];
        float4 vd = x4[sd * 32 + lane];
        m.x = fmaxf(m.x, va.x * wa); m.y = fmaxf(m.y, va.y * wa);
        m.z = fmaxf(m.z, va.z * wa); m.w = fmaxf(m.w, va.w * wa);
        m.x = fmaxf(m.x, vb.x * wb); m.y = fmaxf(m.y, vb.y * wb);
        m.z = fmaxf(m.z, vb.z * wb); m.w = fmaxf(m.w, vb.w * wb);
        m.x = fmaxf(m.x, vc.x * wc); m.y = fmaxf(m.y, vc.y * wc);
        m.z = fmaxf(m.z, vc.z * wc); m.w = fmaxf(m.w, vc.w * wc);
        m.x = fmaxf(m.x, vd.x * wd); m.y = fmaxf(m.y, vd.y * wd);
        m.z = fmaxf(m.z, vd.z * wd); m.w = fmaxf(m.w, vd.w * wd);
    }
    for (; i < s1; i++) {
        int sa = g_src[i]; float wa = g_w[i];
        float4 va = x4[sa * 32 + lane];
        m.x = fmaxf(m.x, va.x * wa); m.y = fmaxf(m.y, va.y * wa);
        m.z = fmaxf(m.z, va.z * wa); m.w = fmaxf(m.w, va.w * wa);
    }
    if (s1 <= s0) m = make_float4(0.f, 0.f, 0.f, 0.f);
    ((float4*)g_aggf)[node * 32 + lane] = m;
}

// ================= HMMA (mma.sync bf16) GEMMs =================
// bf16 smem pitch: 136 bf16 = 272 bytes -> frag loads conflict-free
#define BPITCH 272
#define WMAT_BYTES (128 * BPITCH)   // 34816

// gemm1 smem: bias/gam/bet + W1(hi,lo) + W2(hi,lo) + A(hi,lo)
#define SG_BIAS 0
#define SG_GAM  512
#define SG_BET  1024
#define SG_W1H  1536
#define SG_W1L  (SG_W1H + WMAT_BYTES)
#define SG_W2H  (SG_W1L + WMAT_BYTES)
#define SG_W2L  (SG_W2H + WMAT_BYTES)
#define SG_AHI  (SG_W2L + WMAT_BYTES)
#define SG_ALO  (SG_AHI + WMAT_BYTES)
#define SMEM1_TOTAL (SG_ALO + WMAT_BYTES)   // 210432

// gemm2 smem: bias/gam/bet + W(hi,lo) + A(hi,lo)
#define SH_AHI  (SG_W1L + WMAT_BYTES)
#define SH_ALO  (SH_AHI + WMAT_BYTES)
#define SMEM2_TOTAL (SH_ALO + WMAT_BYTES)   // 140800

__device__ __forceinline__ void mma16816(float* c, uint32_t a0, uint32_t a1,
                                         uint32_t a2, uint32_t a3,
                                         uint32_t b0, uint32_t b1) {
    asm volatile("mma.sync.aligned.m16n8k16.row.col.f32.bf16.bf16.f32 "
        "{%0,%1,%2,%3}, {%4,%5,%6,%7}, {%8,%9}, {%0,%1,%2,%3};"
        : "+f"(c[0]), "+f"(c[1]), "+f"(c[2]), "+f"(c[3])
        : "r"(a0), "r"(a1), "r"(a2), "r"(a3), "r"(b0), "r"(b1));
}

// Stage a [rows<=128, 128] fp32 matrix as bf16 hi + residual lo into pitched smem.
__device__ __forceinline__ void stage_bf16(char* dhi, char* dlo,
                                           const float* __restrict__ src,
                                           int rows_valid, int tid) {
    #pragma unroll 4
    for (int p = tid; p < 128 * 64; p += 256) {
        int r = p >> 6, kp = p & 63;
        float2 v = (r < rows_valid) ? ((const float2*)src)[r * 64 + kp]
                                    : make_float2(0.f, 0.f);
        __nv_bfloat162 hi = __floats2bfloat162_rn(v.x, v.y);
        float rx = v.x - __bfloat162float(__low2bfloat16(hi));
        float ry = v.y - __bfloat162float(__high2bfloat16(hi));
        __nv_bfloat162 lo = __floats2bfloat162_rn(rx, ry);
        *(uint32_t*)(dhi + r * BPITCH + kp * 4) = *reinterpret_cast<uint32_t*>(&hi);
        *(uint32_t*)(dlo + r * BPITCH + kp * 4) = *reinterpret_cast<uint32_t*>(&lo);
    }
}

// One K=128 pass: c[16][4] += A(16-row band) * W^T, 3-term bf16 split.
__device__ __forceinline__ void mma_phase(float c[16][4],
                                          const char* ah_, const char* al_,
                                          const char* wh_, const char* wl_,
                                          int wband, int g, int tig) {
    const char* arh  = ah_ + (wband + g) * BPITCH;
    const char* arh8 = arh + 8 * BPITCH;
    const char* arl  = al_ + (wband + g) * BPITCH;
    const char* arl8 = arl + 8 * BPITCH;
    const char* wh = wh_ + g * BPITCH;
    const char* wl = wl_ + g * BPITCH;
    #pragma unroll 2
    for (int ks = 0; ks < 8; ks++) {
        int kb = ks * 32 + tig * 4;          // (k0 + tig*2) bf16 -> bytes
        uint32_t ah0 = *(const uint32_t*)(arh  + kb);
        uint32_t ah1 = *(const uint32_t*)(arh8 + kb);
        uint32_t ah2 = *(const uint32_t*)(arh  + kb + 16);
        uint32_t ah3 = *(const uint32_t*)(arh8 + kb + 16);
        uint32_t al0 = *(const uint32_t*)(arl  + kb);
        uint32_t al1 = *(const uint32_t*)(arl8 + kb);
        uint32_t al2 = *(const uint32_t*)(arl  + kb + 16);
        uint32_t al3 = *(const uint32_t*)(arl8 + kb + 16);
        #pragma unroll
        for (int nt = 0; nt < 16; nt++) {
            const char* ph = wh + nt * 8 * BPITCH + kb;
            const char* pl = wl + nt * 8 * BPITCH + kb;
            uint32_t bh0 = *(const uint32_t*)(ph);
            uint32_t bh1 = *(const uint32_t*)(ph + 16);
            uint32_t bl0 = *(const uint32_t*)(pl);
            uint32_t bl1 = *(const uint32_t*)(pl + 16);
            mma16816(c[nt], ah0, ah1, ah2, ah3, bh0, bh1);
            mma16816(c[nt], ah0, ah1, ah2, ah3, bl0, bl1);
            mma16816(c[nt], al0, al1, al2, al3, bh0, bh1);
        }
    }
}

// Shared epilogue: gelu(c+bias)+skip, LN over row, store.
__device__ __forceinline__ void epilogue(float c[16][4], const char* smem,
                                         const float* __restrict__ skip,
                                         float* __restrict__ dst,
                                         int row0, int wband, int g, int tig, int n) {
    const float* sb  = (const float*)(smem + SG_BIAS);
    const float* sg_ = (const float*)(smem + SG_GAM);
    const float* sbt = (const float*)(smem + SG_BET);
    int rA = row0 + wband + g;
    int rB = rA + 8;
    float sA = 0.f, qA = 0.f, sB = 0.f, qB = 0.f;
    #pragma unroll
    for (int nt = 0; nt < 16; nt++) {
        int col = nt * 8 + tig * 2;
        float2 xa = (rA < n) ? *(const float2*)(skip + (size_t)rA * 128 + col)
                             : make_float2(0.f, 0.f);
        float2 xb = (rB < n) ? *(const float2*)(skip + (size_t)rB * 128 + col)
                             : make_float2(0.f, 0.f);
        c[nt][0] = gelu_exact(c[nt][0] + sb[col])     + xa.x;
        c[nt][1] = gelu_exact(c[nt][1] + sb[col + 1]) + xa.y;
        c[nt][2] = gelu_exact(c[nt][2] + sb[col])     + xb.x;
        c[nt][3] = gelu_exact(c[nt][3] + sb[col + 1]) + xb.y;
        sA += c[nt][0] + c[nt][1]; qA += c[nt][0] * c[nt][0] + c[nt][1] * c[nt][1];
        sB += c[nt][2] + c[nt][3]; qB += c[nt][2] * c[nt][2] + c[nt][3] * c[nt][3];
    }
    #pragma unroll
    for (int o = 1; o <= 2; o <<= 1) {
        sA += __shfl_xor_sync(0xffffffffu, sA, o);
        qA += __shfl_xor_sync(0xffffffffu, qA, o);
        sB += __shfl_xor_sync(0xffffffffu, sB, o);
        qB += __shfl_xor_sync(0xffffffffu, qB, o);
    }
    float muA = sA * (1.f / D);
    float rsA = rsqrtf(fmaxf(qA * (1.f / D) - muA * muA, 0.f) + LN_EPS);
    float muB = sB * (1.f / D);
    float rsB = rsqrtf(fmaxf(qB * (1.f / D) - muB * muB, 0.f) + LN_EPS);
    #pragma unroll
    for (int nt = 0; nt < 16; nt++) {
        int col = nt * 8 + tig * 2;
        if (rA < n) {
            float2 y;
            y.x = (c[nt][0] - muA) * rsA * sg_[col]     + sbt[col];
            y.y = (c[nt][1] - muA) * rsA * sg_[col + 1] + sbt[col + 1];
            *(float2*)(dst + (size_t)rA * 128 + col) = y;
        }
        if (rB < n) {
            float2 y;
            y.x = (c[nt][2] - muB) * rsB * sg_[col]     + sbt[col];
            y.y = (c[nt][3] - muB) * rsB * sg_[col + 1] + sbt[col + 1];
            *(float2*)(dst + (size_t)rB * 128 + col) = y;
        }
    }
}

// h = LN( gelu(agg@Wrel^T + b + x@Wroot^T) + x )
__global__ void __launch_bounds__(256, 1)
k_gemm1_mma(const float* __restrict__ x, const float* __restrict__ Wrel,
            const float* __restrict__ brel, const float* __restrict__ Wroot,
            const float* __restrict__ gamma, const float* __restrict__ beta, int n) {
    extern __shared__ char smem[];
    int tid = threadIdx.x, lane = tid & 31, wp = tid >> 5;
    int g = lane >> 2, tig = lane & 3, wband = wp * 16;

    stage_bf16(smem + SG_W1H, smem + SG_W1L, Wrel, 128, tid);
    stage_bf16(smem + SG_W2H, smem + SG_W2L, Wroot, 128, tid);
    if (tid < 128) {
        ((float*)(smem + SG_BIAS))[tid] = brel[tid];
        ((float*)(smem + SG_GAM))[tid]  = gamma[tid];
        ((float*)(smem + SG_BET))[tid]  = beta[tid];
    }
    __syncthreads();

    int nch = (n + 127) >> 7;
    for (int ch = blockIdx.x; ch < nch; ch += gridDim.x) {
        int row0 = ch << 7;
        int rv = n - row0; if (rv > 128) rv = 128;
        float c[16][4];
        #pragma unroll
        for (int t = 0; t < 16; t++)
            c[t][0] = c[t][1] = c[t][2] = c[t][3] = 0.f;

        stage_bf16(smem + SG_AHI, smem + SG_ALO, g_aggf + (size_t)row0 * 128, rv, tid);
        __syncthreads();
        mma_phase(c, smem + SG_AHI, smem + SG_ALO, smem + SG_W1H, smem + SG_W1L,
                  wband, g, tig);
        __syncthreads();
        stage_bf16(smem + SG_AHI, smem + SG_ALO, x + (size_t)row0 * 128, rv, tid);
        __syncthreads();
        mma_phase(c, smem + SG_AHI, smem + SG_ALO, smem + SG_W2H, smem + SG_W2L,
                  wband, g, tig);

        epilogue(c, smem, x, g_h, row0, wband, g, tig, n);
        __syncthreads();
    }
}

// out = LN( gelu(h@linW^T + lb) + h )
__global__ void __launch_bounds__(256, 1)
k_gemm2_mma(const float* __restrict__ lw, const float* __restrict__ lb,
            const float* __restrict__ gamma, const float* __restrict__ beta,
            float* __restrict__ out, int n) {
    extern __shared__ char smem[];
    int tid = threadIdx.x, lane = tid & 31, wp = tid >> 5;
    int g = lane >> 2, tig = lane & 3, wband = wp * 16;

    stage_bf16(smem + SG_W1H, smem + SG_W1L, lw, 128, tid);
    if (tid < 128) {
        ((float*)(smem + SG_BIAS))[tid] = lb[tid];
        ((float*)(smem + SG_GAM))[tid]  = gamma[tid];
        ((float*)(smem + SG_BET))[tid]  = beta[tid];
    }
    __syncthreads();

    int nch = (n + 127) >> 7;
    for (int ch = blockIdx.x; ch < nch; ch += gridDim.x) {
        int row0 = ch << 7;
        int rv = n - row0; if (rv > 128) rv = 128;
        float c[16][4];
        #pragma unroll
        for (int t = 0; t < 16; t++)
            c[t][0] = c[t][1] = c[t][2] = c[t][3] = 0.f;

        stage_bf16(smem + SH_AHI, smem + SH_ALO, g_h + (size_t)row0 * 128, rv, tid);
        __syncthreads();
        mma_phase(c, smem + SH_AHI, smem + SH_ALO, smem + SG_W1H, smem + SG_W1L,
                  wband, g, tig);

        epilogue(c, smem, g_h, out, row0, wband, g, tig, n);
        __syncthreads();
    }
}

// ---------------- launch ----------------
extern "C" void kernel_launch(void* const* d_in, const int* in_sizes, int n_in,
                              void* d_out, int out_size) {
    const float* x     = (const float*)d_in[0];
    const int*   ei    = (const int*)d_in[1];
    const float* ew    = (const float*)d_in[2];
    const float* Wrel  = (const float*)d_in[3];
    const float* brel  = (const float*)d_in[4];
    const float* Wroot = (const float*)d_in[5];
    const float* linW  = (const float*)d_in[6];
    const float* linb  = (const float*)d_in[7];
    const float* gamma = (const float*)d_in[8];
    const float* beta  = (const float*)d_in[9];
    float* out = (float*)d_out;

    int n = in_sizes[0] / D;
    int e = in_sizes[2];
    int nsb = (n + 1023) / 1024;

    cudaFuncSetAttribute(k_gemm1_mma, cudaFuncAttributeMaxDynamicSharedMemorySize, SMEM1_TOTAL);
    cudaFuncSetAttribute(k_gemm2_mma, cudaFuncAttributeMaxDynamicSharedMemorySize, SMEM2_TOTAL);

    k_prep<<<(n + 255) / 256, 256>>>(ei, n);
    k_count<<<(e + 255) / 256, 256>>>(ei, e);
    k_scan1<<<nsb, 1024>>>(n);
    k_scan2<<<nsb, 1024>>>(n);
    k_place<<<(e + 255) / 256, 256>>>(ei, ew, e);
    k_agg<<<(n + 7) / 8, 256>>>(x, n);
    k_gemm1_mma<<<148, 256, SMEM1_TOTAL>>>(x, Wrel, brel, Wroot, gamma, beta, n);
    k_gemm2_mma<<<148, 256, SMEM2_TOTAL>>>(linW, linb, gamma, beta, out, n);
    if (out_size >= n * D + e)
        cudaMemcpyAsync(out + (size_t)n * D, ew, (size_t)e * sizeof(float),
                        cudaMemcpyDeviceToDevice);
}

// round 14
// speedup vs baseline: 1.3938x; 1.0400x over previous
#include <cuda_runtime.h>
#include <cuda_bf16.h>
#include <math.h>
#include <stdint.h>

#define D 128
#define NMAX 20000
#define EMAX 640000
#define LN_EPS 1e-5f

// ---------------- device scratch (no allocs allowed) ----------------
__device__ float g_aggf[NMAX * D];     // segment-max result (0 for empty)
__device__ float g_h[NMAX * D];        // h after first LayerNorm
__device__ float g_xw[NMAX * D];       // x @ Wroot^T (computed on side stream)
__device__ int   g_cnt[NMAX];          // per-node degree counters
__device__ int   g_off[NMAX + 1];      // CSR offsets
__device__ int   g_bsum[64];           // per-scan-block sums
__device__ int   g_pos[EMAX];          // per-edge slot within its dst bucket
__device__ int   g_src[EMAX];          // CSR-ordered source ids
__device__ float g_w[EMAX];            // CSR-ordered edge weights
__device__ int   g_i64;                // 1 if edge_index buffer is int64

__device__ __forceinline__ float gelu_exact(float v) { return v * normcdff(v); }

// ---------------- K0: detect int64 + zero counters ----------------
__global__ void k_prep(const int* __restrict__ ei, int n) {
    int i = blockIdx.x * blockDim.x + threadIdx.x;
    if (i < n) g_cnt[i] = 0;
    if (blockIdx.x == 0) {
        __shared__ int bad;
        if (threadIdx.x == 0) bad = 0;
        __syncthreads();
        int any = 0;
        for (int j = threadIdx.x; j < 1024; j += blockDim.x)
            if (ei[2 * j + 1] != 0) any = 1;
        if (any) atomicOr(&bad, 1);
        __syncthreads();
        if (threadIdx.x == 0) g_i64 = (bad == 0) ? 1 : 0;
    }
}

__global__ void k_count(const int* __restrict__ ei, int e) {
    int i = blockIdx.x * blockDim.x + threadIdx.x;
    if (i >= e) return;
    int dst = g_i64 ? ei[2 * (e + i)] : ei[e + i];
    g_pos[i] = atomicAdd(&g_cnt[dst], 1);
}

// ---------------- parallel scan ----------------
__global__ void k_scan1(int n) {
    __shared__ int wsum[32];
    int i = blockIdx.x * 1024 + threadIdx.x;
    int lane = threadIdx.x & 31, wid = threadIdx.x >> 5;
    int v = (i < n) ? g_cnt[i] : 0;
    #pragma unroll
    for (int o = 16; o; o >>= 1) v += __shfl_xor_sync(0xffffffffu, v, o);
    if (lane == 0) wsum[wid] = v;
    __syncthreads();
    if (wid == 0) {
        int s = wsum[lane];
        #pragma unroll
        for (int o = 16; o; o >>= 1) s += __shfl_xor_sync(0xffffffffu, s, o);
        if (lane == 0) g_bsum[blockIdx.x] = s;
    }
}

__global__ void k_scan2(int n) {
    __shared__ int wsum[32];
    __shared__ int prefix_s;
    int tid = threadIdx.x, lane = tid & 31, wid = tid >> 5;
    int b = blockIdx.x;
    if (tid == 0) {
        int p = 0;
        for (int j = 0; j < b; j++) p += g_bsum[j];
        prefix_s = p;
    }
    int i = b * 1024 + tid;
    int v = (i < n) ? g_cnt[i] : 0;
    int s = v;
    #pragma unroll
    for (int o = 1; o < 32; o <<= 1) {
        int t = __shfl_up_sync(0xffffffffu, s, o);
        if (lane >= o) s += t;
    }
    if (lane == 31) wsum[wid] = s;
    __syncthreads();
    if (wid == 0) {
        int ws = wsum[lane];
        #pragma unroll
        for (int o = 1; o < 32; o <<= 1) {
            int t = __shfl_up_sync(0xffffffffu, ws, o);
            if (lane >= o) ws += t;
        }
        wsum[lane] = ws;
    }
    __syncthreads();
    int prefix = prefix_s;
    int excl = prefix + s - v + (wid > 0 ? wsum[wid - 1] : 0);
    if (i < n) g_off[i] = excl;
    if (b == gridDim.x - 1 && tid == 0) g_off[n] = prefix + wsum[31];
}

__global__ void k_place(const int* __restrict__ ei, const float* __restrict__ ew, int e) {
    int i = blockIdx.x * blockDim.x + threadIdx.x;
    if (i >= e) return;
    int src, dst;
    if (g_i64) { src = ei[2 * i]; dst = ei[2 * (e + i)]; }
    else       { src = ei[i];     dst = ei[e + i]; }
    int idx = g_off[dst] + g_pos[i];
    g_src[idx] = src;
    g_w[idx]   = ew[i];
}

// ---------------- per-node gather-max: one warp per node ----------------
__global__ void k_agg(const float* __restrict__ x, int n) {
    int wp = threadIdx.x >> 5, lane = threadIdx.x & 31;
    int node = blockIdx.x * 8 + wp;
    if (node >= n) return;
    int s0 = g_off[node], s1 = g_off[node + 1];
    const float4* x4 = (const float4*)x;
    float4 m = make_float4(-INFINITY, -INFINITY, -INFINITY, -INFINITY);
    int i = s0;
    for (; i + 3 < s1; i += 4) {
        int sa = g_src[i], sb = g_src[i + 1], sc = g_src[i + 2], sd = g_src[i + 3];
        float wa = g_w[i], wb = g_w[i + 1], wc = g_w[i + 2], wd = g_w[i + 3];
        float4 va = __ldcg(&x4[sa * 32 + lane]);
        float4 vb = __ldcg(&x4[sb * 32 + lane]);
        float4 vc = __ldcg(&x4[sc * 32 + lane]);
        float4 vd = __ldcg(&x4[sd * 32 + lane]);
        m.x = fmaxf(m.x, va.x * wa); m.y = fmaxf(m.y, va.y * wa);
        m.z = fmaxf(m.z, va.z * wa); m.w = fmaxf(m.w, va.w * wa);
        m.x = fmaxf(m.x, vb.x * wb); m.y = fmaxf(m.y, vb.y * wb);
        m.z = fmaxf(m.z, vb.z * wb); m.w = fmaxf(m.w, vb.w * wb);
        m.x = fmaxf(m.x, vc.x * wc); m.y = fmaxf(m.y, vc.y * wc);
        m.z = fmaxf(m.z, vc.z * wc); m.w = fmaxf(m.w, vc.w * wc);
        m.x = fmaxf(m.x, vd.x * wd); m.y = fmaxf(m.y, vd.y * wd);
        m.z = fmaxf(m.z, vd.z * wd); m.w = fmaxf(m.w, vd.w * wd);
    }
    for (; i < s1; i++) {
        int sa = g_src[i]; float wa = g_w[i];
        float4 va = __ldcg(&x4[sa * 32 + lane]);
        m.x = fmaxf(m.x, va.x * wa); m.y = fmaxf(m.y, va.y * wa);
        m.z = fmaxf(m.z, va.z * wa); m.w = fmaxf(m.w, va.w * wa);
    }
    if (s1 <= s0) m = make_float4(0.f, 0.f, 0.f, 0.f);
    ((float4*)g_aggf)[node * 32 + lane] = m;
}

// ================= HMMA (mma.sync bf16) GEMMs =================
#define BPITCH 272
#define WMAT_BYTES (128 * BPITCH)   // 34816

// common smem layout: bias/gam/bet + W(hi,lo) + A(hi,lo)
#define SG_BIAS 0
#define SG_GAM  512
#define SG_BET  1024
#define SG_W1H  1536
#define SG_W1L  (SG_W1H + WMAT_BYTES)
#define SH_AHI  (SG_W1L + WMAT_BYTES)
#define SH_ALO  (SH_AHI + WMAT_BYTES)
#define SMEM_GEMM (SH_ALO + WMAT_BYTES)   // 140800

__device__ __forceinline__ void mma16816(float* c, uint32_t a0, uint32_t a1,
                                         uint32_t a2, uint32_t a3,
                                         uint32_t b0, uint32_t b1) {
    asm volatile("mma.sync.aligned.m16n8k16.row.col.f32.bf16.bf16.f32 "
        "{%0,%1,%2,%3}, {%4,%5,%6,%7}, {%8,%9}, {%0,%1,%2,%3};"
        : "+f"(c[0]), "+f"(c[1]), "+f"(c[2]), "+f"(c[3])
        : "r"(a0), "r"(a1), "r"(a2), "r"(a3), "r"(b0), "r"(b1));
}

__device__ __forceinline__ void stage_bf16(char* dhi, char* dlo,
                                           const float* __restrict__ src,
                                           int rows_valid, int tid) {
    #pragma unroll 4
    for (int p = tid; p < 128 * 64; p += 256) {
        int r = p >> 6, kp = p & 63;
        float2 v = (r < rows_valid) ? ((const float2*)src)[r * 64 + kp]
                                    : make_float2(0.f, 0.f);
        __nv_bfloat162 hi = __floats2bfloat162_rn(v.x, v.y);
        float rx = v.x - __bfloat162float(__low2bfloat16(hi));
        float ry = v.y - __bfloat162float(__high2bfloat16(hi));
        __nv_bfloat162 lo = __floats2bfloat162_rn(rx, ry);
        *(uint32_t*)(dhi + r * BPITCH + kp * 4) = *reinterpret_cast<uint32_t*>(&hi);
        *(uint32_t*)(dlo + r * BPITCH + kp * 4) = *reinterpret_cast<uint32_t*>(&lo);
    }
}

// One K=128 pass: c[16][4] += A(16-row band) * W^T, 3-term bf16 split.
__device__ __forceinline__ void mma_phase(float c[16][4],
                                          const char* ah_, const char* al_,
                                          const char* wh_, const char* wl_,
                                          int wband, int g, int tig) {
    const char* arh  = ah_ + (wband + g) * BPITCH;
    const char* arh8 = arh + 8 * BPITCH;
    const char* arl  = al_ + (wband + g) * BPITCH;
    const char* arl8 = arl + 8 * BPITCH;
    const char* wh = wh_ + g * BPITCH;
    const char* wl = wl_ + g * BPITCH;
    #pragma unroll 2
    for (int ks = 0; ks < 8; ks++) {
        int kb = ks * 32 + tig * 4;
        uint32_t ah0 = *(const uint32_t*)(arh  + kb);
        uint32_t ah1 = *(const uint32_t*)(arh8 + kb);
        uint32_t ah2 = *(const uint32_t*)(arh  + kb + 16);
        uint32_t ah3 = *(const uint32_t*)(arh8 + kb + 16);
        uint32_t al0 = *(const uint32_t*)(arl  + kb);
        uint32_t al1 = *(const uint32_t*)(arl8 + kb);
        uint32_t al2 = *(const uint32_t*)(arl  + kb + 16);
        uint32_t al3 = *(const uint32_t*)(arl8 + kb + 16);
        #pragma unroll
        for (int nt = 0; nt < 16; nt++) {
            const char* ph = wh + nt * 8 * BPITCH + kb;
            const char* pl = wl + nt * 8 * BPITCH + kb;
            uint32_t bh0 = *(const uint32_t*)(ph);
            uint32_t bh1 = *(const uint32_t*)(ph + 16);
            uint32_t bl0 = *(const uint32_t*)(pl);
            uint32_t bl1 = *(const uint32_t*)(pl + 16);
            mma16816(c[nt], ah0, ah1, ah2, ah3, bh0, bh1);
            mma16816(c[nt], ah0, ah1, ah2, ah3, bl0, bl1);
            mma16816(c[nt], al0, al1, al2, al3, bh0, bh1);
        }
    }
}

// gemm2-style epilogue: gelu(c+bias)+skip, LN, store.
__device__ __forceinline__ void epilogue(float c[16][4], const char* smem,
                                         const float* __restrict__ skip,
                                         float* __restrict__ dst,
                                         int row0, int wband, int g, int tig, int n) {
    const float* sb  = (const float*)(smem + SG_BIAS);
    const float* sg_ = (const float*)(smem + SG_GAM);
    const float* sbt = (const float*)(smem + SG_BET);
    int rA = row0 + wband + g;
    int rB = rA + 8;
    float sA = 0.f, qA = 0.f, sB = 0.f, qB = 0.f;
    #pragma unroll
    for (int nt = 0; nt < 16; nt++) {
        int col = nt * 8 + tig * 2;
        float2 xa = (rA < n) ? *(const float2*)(skip + (size_t)rA * 128 + col)
                             : make_float2(0.f, 0.f);
        float2 xb = (rB < n) ? *(const float2*)(skip + (size_t)rB * 128 + col)
                             : make_float2(0.f, 0.f);
        c[nt][0] = gelu_exact(c[nt][0] + sb[col])     + xa.x;
        c[nt][1] = gelu_exact(c[nt][1] + sb[col + 1]) + xa.y;
        c[nt][2] = gelu_exact(c[nt][2] + sb[col])     + xb.x;
        c[nt][3] = gelu_exact(c[nt][3] + sb[col + 1]) + xb.y;
        sA += c[nt][0] + c[nt][1]; qA += c[nt][0] * c[nt][0] + c[nt][1] * c[nt][1];
        sB += c[nt][2] + c[nt][3]; qB += c[nt][2] * c[nt][2] + c[nt][3] * c[nt][3];
    }
    #pragma unroll
    for (int o = 1; o <= 2; o <<= 1) {
        sA += __shfl_xor_sync(0xffffffffu, sA, o);
        qA += __shfl_xor_sync(0xffffffffu, qA, o);
        sB += __shfl_xor_sync(0xffffffffu, sB, o);
        qB += __shfl_xor_sync(0xffffffffu, qB, o);
    }
    float muA = sA * (1.f / D);
    float rsA = rsqrtf(fmaxf(qA * (1.f / D) - muA * muA, 0.f) + LN_EPS);
    float muB = sB * (1.f / D);
    float rsB = rsqrtf(fmaxf(qB * (1.f / D) - muB * muB, 0.f) + LN_EPS);
    #pragma unroll
    for (int nt = 0; nt < 16; nt++) {
        int col = nt * 8 + tig * 2;
        if (rA < n) {
            float2 y;
            y.x = (c[nt][0] - muA) * rsA * sg_[col]     + sbt[col];
            y.y = (c[nt][1] - muA) * rsA * sg_[col + 1] + sbt[col + 1];
            *(float2*)(dst + (size_t)rA * 128 + col) = y;
        }
        if (rB < n) {
            float2 y;
            y.x = (c[nt][2] - muB) * rsB * sg_[col]     + sbt[col];
            y.y = (c[nt][3] - muB) * rsB * sg_[col + 1] + sbt[col + 1];
            *(float2*)(dst + (size_t)rB * 128 + col) = y;
        }
    }
}

// ---- side-stream kernel: g_xw = x @ Wroot^T (raw fp32) ----
__global__ void __launch_bounds__(256, 1)
k_xroot(const float* __restrict__ x, const float* __restrict__ Wroot, int n) {
    extern __shared__ char smem[];
    int tid = threadIdx.x, lane = tid & 31, wp = tid >> 5;
    int g = lane >> 2, tig = lane & 3, wband = wp * 16;

    stage_bf16(smem + SG_W1H, smem + SG_W1L, Wroot, 128, tid);
    __syncthreads();

    int nch = (n + 127) >> 7;
    for (int ch = blockIdx.x; ch < nch; ch += gridDim.x) {
        int row0 = ch << 7;
        int rv = n - row0; if (rv > 128) rv = 128;
        float c[16][4];
        #pragma unroll
        for (int t = 0; t < 16; t++)
            c[t][0] = c[t][1] = c[t][2] = c[t][3] = 0.f;

        stage_bf16(smem + SH_AHI, smem + SH_ALO, x + (size_t)row0 * 128, rv, tid);
        __syncthreads();
        mma_phase(c, smem + SH_AHI, smem + SH_ALO, smem + SG_W1H, smem + SG_W1L,
                  wband, g, tig);

        int rA = row0 + wband + g, rB = rA + 8;
        #pragma unroll
        for (int nt = 0; nt < 16; nt++) {
            int col = nt * 8 + tig * 2;
            if (rA < n) *(float2*)(g_xw + (size_t)rA * 128 + col)
                        = make_float2(c[nt][0], c[nt][1]);
            if (rB < n) *(float2*)(g_xw + (size_t)rB * 128 + col)
                        = make_float2(c[nt][2], c[nt][3]);
        }
        __syncthreads();
    }
}

// h = LN( gelu(agg@Wrel^T + b + xw) + x )   [xw precomputed on side stream]
__global__ void __launch_bounds__(256, 1)
k_gemm1_mma(const float* __restrict__ x, const float* __restrict__ Wrel,
            const float* __restrict__ brel,
            const float* __restrict__ gamma, const float* __restrict__ beta, int n) {
    extern __shared__ char smem[];
    int tid = threadIdx.x, lane = tid & 31, wp = tid >> 5;
    int g = lane >> 2, tig = lane & 3, wband = wp * 16;

    stage_bf16(smem + SG_W1H, smem + SG_W1L, Wrel, 128, tid);
    if (tid < 128) {
        ((float*)(smem + SG_BIAS))[tid] = brel[tid];
        ((float*)(smem + SG_GAM))[tid]  = gamma[tid];
        ((float*)(smem + SG_BET))[tid]  = beta[tid];
    }
    __syncthreads();

    int nch = (n + 127) >> 7;
    for (int ch = blockIdx.x; ch < nch; ch += gridDim.x) {
        int row0 = ch << 7;
        int rv = n - row0; if (rv > 128) rv = 128;
        float c[16][4];
        #pragma unroll
        for (int t = 0; t < 16; t++)
            c[t][0] = c[t][1] = c[t][2] = c[t][3] = 0.f;

        stage_bf16(smem + SH_AHI, smem + SH_ALO, g_aggf + (size_t)row0 * 128, rv, tid);
        __syncthreads();
        mma_phase(c, smem + SH_AHI, smem + SH_ALO, smem + SG_W1H, smem + SG_W1L,
                  wband, g, tig);

        // fold in xw before the shared epilogue's gelu
        int rA = row0 + wband + g, rB = rA + 8;
        #pragma unroll
        for (int nt = 0; nt < 16; nt++) {
            int col = nt * 8 + tig * 2;
            float2 wa = (rA < n) ? *(const float2*)(g_xw + (size_t)rA * 128 + col)
                                 : make_float2(0.f, 0.f);
            float2 wb = (rB < n) ? *(const float2*)(g_xw + (size_t)rB * 128 + col)
                                 : make_float2(0.f, 0.f);
            c[nt][0] += wa.x; c[nt][1] += wa.y;
            c[nt][2] += wb.x; c[nt][3] += wb.y;
        }
        epilogue(c, smem, x, g_h, row0, wband, g, tig, n);
        __syncthreads();
    }
}

// out = LN( gelu(h@linW^T + lb) + h )
__global__ void __launch_bounds__(256, 1)
k_gemm2_mma(const float* __restrict__ lw, const float* __restrict__ lb,
            const float* __restrict__ gamma, const float* __restrict__ beta,
            float* __restrict__ out, int n) {
    extern __shared__ char smem[];
    int tid = threadIdx.x, lane = tid & 31, wp = tid >> 5;
    int g = lane >> 2, tig = lane & 3, wband = wp * 16;

    stage_bf16(smem + SG_W1H, smem + SG_W1L, lw, 128, tid);
    if (tid < 128) {
        ((float*)(smem + SG_BIAS))[tid] = lb[tid];
        ((float*)(smem + SG_GAM))[tid]  = gamma[tid];
        ((float*)(smem + SG_BET))[tid]  = beta[tid];
    }
    __syncthreads();

    int nch = (n + 127) >> 7;
    for (int ch = blockIdx.x; ch < nch; ch += gridDim.x) {
        int row0 = ch << 7;
        int rv = n - row0; if (rv > 128) rv = 128;
        float c[16][4];
        #pragma unroll
        for (int t = 0; t < 16; t++)
            c[t][0] = c[t][1] = c[t][2] = c[t][3] = 0.f;

        stage_bf16(smem + SH_AHI, smem + SH_ALO, g_h + (size_t)row0 * 128, rv, tid);
        __syncthreads();
        mma_phase(c, smem + SH_AHI, smem + SH_ALO, smem + SG_W1H, smem + SG_W1L,
                  wband, g, tig);

        epilogue(c, smem, g_h, out, row0, wband, g, tig, n);
        __syncthreads();
    }
}

// ---------------- launch ----------------
extern "C" void kernel_launch(void* const* d_in, const int* in_sizes, int n_in,
                              void* d_out, int out_size) {
    const float* x     = (const float*)d_in[0];
    const int*   ei    = (const int*)d_in[1];
    const float* ew    = (const float*)d_in[2];
    const float* Wrel  = (const float*)d_in[3];
    const float* brel  = (const float*)d_in[4];
    const float* Wroot = (const float*)d_in[5];
    const float* linW  = (const float*)d_in[6];
    const float* linb  = (const float*)d_in[7];
    const float* gamma = (const float*)d_in[8];
    const float* beta  = (const float*)d_in[9];
    float* out = (float*)d_out;

    int n = in_sizes[0] / D;
    int e = in_sizes[2];
    int nsb = (n + 1023) / 1024;

    cudaFuncSetAttribute(k_xroot,     cudaFuncAttributeMaxDynamicSharedMemorySize, SMEM_GEMM);
    cudaFuncSetAttribute(k_gemm1_mma, cudaFuncAttributeMaxDynamicSharedMemorySize, SMEM_GEMM);
    cudaFuncSetAttribute(k_gemm2_mma, cudaFuncAttributeMaxDynamicSharedMemorySize, SMEM_GEMM);

    // fork side stream off the capture stream
    cudaStream_t s2;
    cudaStreamCreateWithFlags(&s2, cudaStreamNonBlocking);
    cudaEvent_t evF, evJ;
    cudaEventCreateWithFlags(&evF, cudaEventDisableTiming);
    cudaEventCreateWithFlags(&evJ, cudaEventDisableTiming);

    cudaEventRecord(evF, 0);
    cudaStreamWaitEvent(s2, evF, 0);
    // side stream: x@Wroot^T and the edge-weight tail copy (independent of agg)
    k_xroot<<<148, 256, SMEM_GEMM, s2>>>(x, Wroot, n);
    if (out_size >= n * D + e)
        cudaMemcpyAsync(out + (size_t)n * D, ew, (size_t)e * sizeof(float),
                        cudaMemcpyDeviceToDevice, s2);
    cudaEventRecord(evJ, s2);

    // main stream: scatter pipeline
    k_prep<<<(n + 255) / 256, 256>>>(ei, n);
    k_count<<<(e + 255) / 256, 256>>>(ei, e);
    k_scan1<<<nsb, 1024>>>(n);
    k_scan2<<<nsb, 1024>>>(n);
    k_place<<<(e + 255) / 256, 256>>>(ei, ew, e);
    k_agg<<<(n + 7) / 8, 256>>>(x, n);

    // join, then fused GEMM chain
    cudaStreamWaitEvent(0, evJ, 0);
    k_gemm1_mma<<<148, 256, SMEM_GEMM>>>(x, Wrel, brel, gamma, beta, n);
    k_gemm2_mma<<<148, 256, SMEM_GEMM>>>(linW, linb, gamma, beta, out, n);
    // note: s2/evF/evJ intentionally not destroyed — the capture may still
    // reference them; kernel_launch is invoked only a handful of times.
}